// round 12
// baseline (speedup 1.0000x reference)
#include <cuda_runtime.h>
#include <math.h>

#define NN 100000
#define NE 1200000
#define KP1 4096
#define KP2 256
#define SLOPE 0.01f
#define EC 65536
#define NB 148
#define NT 1024
#define NTH (NB*NT)
#define NCH 98            // ceil(NN/1024), chunk = 1024 = NT

// ---------------- scratch (no allocations) ----------------
__device__ int      g_degi[NN];
__device__ double   g_ddinv[NN];
__device__ double   g_dagg3[NN * 3];       // aliased later as x2 floats
__device__ unsigned g_keys1[NN];
__device__ int      g_inv1[NN];
__device__ float    g_B[524288];           // [x1p | agg64]
__device__ float    g_C[524288];           // agg128

#define G_X2     ((float*)g_dagg3)         /* [KP1*128] after dagg3 dead */
#define G_X1P    (g_B)
#define G_AGG64  (g_B + 262144)
#define G_AGG128 (g_C)

__device__ unsigned g_hist[256];
__device__ unsigned g_prefix;
__device__ int      g_kst;
__device__ int      g_cg[NCH], g_ce[NCH], g_ceOff[NCH], g_keptOff[NCH];
__device__ int      g_sel1[KP1], g_sel1s[KP1];
__device__ unsigned long long g_ck[KP1];
__device__ int      g_rank[KP1];
__device__ int2     g_edge[EC];
__device__ int      g_ne1;
__device__ float    g_dinv2[KP1];
__device__ float    g_sc2[KP1];
__device__ float    g_xflat[KP2 * 256];
__device__ float    g_invp1;
__device__ double   g_invp2d;
__device__ unsigned g_barc, g_barg;        // zero-init; self-resetting

__device__ __forceinline__ float leaky(float v) { return v > 0.f ? v : SLOPE * v; }
__device__ __forceinline__ unsigned fkey(float f) {
    unsigned u = __float_as_uint(f);
    return (u & 0x80000000u) ? ~u : (u | 0x80000000u);
}
__device__ __forceinline__ float ikey(unsigned k) {
    return __uint_as_float((k & 0x80000000u) ? (k ^ 0x80000000u) : ~k);
}

// software grid barrier: NB blocks, 1/SM, all resident -> no deadlock.
__device__ __forceinline__ void gridbar() {
    __syncthreads();
    if (threadIdx.x == 0) {
        unsigned gen = atomicAdd(&g_barg, 0u);
        __threadfence();
        if (atomicAdd(&g_barc, 1u) == NB - 1u) {
            atomicExch(&g_barc, 0u);
            __threadfence();
            atomicAdd(&g_barg, 1u);
        } else {
            while (atomicAdd(&g_barg, 0u) == gen) __nanosleep(64);
        }
        __threadfence();
    }
    __syncthreads();
}

// ---------------- 1) setup (normal wide kernel) ----------------
__global__ void k_setup(const float* __restrict__ p1, const float* __restrict__ p2,
                        const float* __restrict__ fcb, float* __restrict__ out) {
    int gid = blockIdx.x * blockDim.x + threadIdx.x;
    int st = gridDim.x * blockDim.x;
    for (int i = gid; i < NN; i += st) g_degi[i] = 0;
    for (int i = gid; i < NN * 3; i += st) g_dagg3[i] = 0.0;
    for (int i = gid; i < KP1; i += st) g_dinv2[i] = 0.f;
    for (int i = gid; i < 524288; i += st) g_C[i] = 0.f;
    for (int i = gid; i < 262144; i += st) g_B[262144 + i] = 0.f;
    if (gid < 256) g_hist[gid] = 0;
    if (gid < 512) out[gid] = fcb[gid];
    if (gid == 0) {
        g_ne1 = 0;
        double s = 0.0;
        for (int i = 0; i < 64; i++) { double v = (double)p1[i]; s += v * v; }
        g_invp1 = (float)(1.0 / sqrt(s));
        double s2 = 0.0;
        for (int i = 0; i < 256; i++) { double v = (double)p2[i]; s2 += v * v; }
        g_invp2d = 1.0 / sqrt(s2);
    }
}

// ---------------- 2) conv1 persistent: deg | dinv | agg3 | score1 ----------------
__global__ void __launch_bounds__(NT, 1)
k_conv1(const int* __restrict__ src, const int* __restrict__ dst,
        const float* __restrict__ pos, const float* __restrict__ W1,
        const float* __restrict__ b1, const float* __restrict__ p1) {
    int t = threadIdx.x, gid = blockIdx.x * NT + t;
    const int4* dst4 = (const int4*)dst;
    const int4* src4 = (const int4*)src;
    for (int q = gid; q < NE / 4; q += NTH) {
        int4 d = dst4[q];
        atomicAdd(&g_degi[d.x], 1); atomicAdd(&g_degi[d.y], 1);
        atomicAdd(&g_degi[d.z], 1); atomicAdd(&g_degi[d.w], 1);
    }
    gridbar();
    for (int i = gid; i < NN; i += NTH) g_ddinv[i] = 1.0 / sqrt((double)g_degi[i] + 1.0);
    gridbar();
    for (int q = gid; q < NE / 4; q += NTH) {    // accumulate pos[s]*dinv[s]; dinv[d] applied later
        int4 s4 = src4[q]; int4 d4 = dst4[q];
        int ss[4] = {s4.x, s4.y, s4.z, s4.w};
        int dd[4] = {d4.x, d4.y, d4.z, d4.w};
#pragma unroll
        for (int j = 0; j < 4; j++) {
            int s = ss[j], d = dd[j];
            double ds = g_ddinv[s];
            atomicAdd(&g_dagg3[d * 3 + 0], (double)pos[s * 3 + 0] * ds);
            atomicAdd(&g_dagg3[d * 3 + 1], (double)pos[s * 3 + 1] * ds);
            atomicAdd(&g_dagg3[d * 3 + 2], (double)pos[s * 3 + 2] * ds);
        }
    }
    gridbar();
    __shared__ float sW[192], sb[64], sp[64];
    if (t < 192) sW[t] = W1[t];
    if (t < 64) { sb[t] = b1[t]; sp[t] = p1[t]; }
    __syncthreads();
    float ip1 = g_invp1;
    for (int i = gid; i < NN; i += NTH) {
        double dd = g_ddinv[i], d2 = dd * dd;
        float c0 = (float)(g_dagg3[3 * i + 0] * dd + (double)pos[3 * i + 0] * d2);
        float c1 = (float)(g_dagg3[3 * i + 1] * dd + (double)pos[3 * i + 1] * d2);
        float c2 = (float)(g_dagg3[3 * i + 2] * dd + (double)pos[3 * i + 2] * d2);
        float s = 0.f;
#pragma unroll
        for (int f = 0; f < 64; f++) {
            float v = sb[f] + c0 * sW[f] + c1 * sW[64 + f] + c2 * sW[128 + f];
            s += leaky(v) * sp[f];
        }
        g_keys1[i] = fkey(tanhf(s * ip1));
    }
}

// ---------------- 3) pool1 persistent: radix, compact, rank1, x1p, filter, agg64, x2, agg128 ----------------
__global__ void __launch_bounds__(NT, 1)
k_pool1(const int* __restrict__ src, const int* __restrict__ dst,
        const float* __restrict__ pos, const float* __restrict__ W1,
        const float* __restrict__ b1, const float* __restrict__ W2,
        const float* __restrict__ b2) {
    int t = threadIdx.x, gid = blockIdx.x * NT + t;
    int lane = t & 31, wid = t >> 5;
    __shared__ unsigned sh_h[256];
    __shared__ int sw[32], swo[32];
    __shared__ int sg, se;
    __shared__ float sW2[64 * 128];           // 32 KB
    __shared__ float shx[16 * 64];            // 4 KB
    __shared__ float sb2[128];
    __shared__ unsigned long long sj[256];    // 2 KB

    // ---- radix select: 4 rounds of 8 bits ----
#pragma unroll 1
    for (int round = 0; round < 4; round++) {
        int shift = 24 - 8 * round;
        if (t < 256) sh_h[t] = 0;
        __syncthreads();
        unsigned pr = (round == 0) ? 0u : __ldcg(&g_prefix);
        for (int i = gid; i < NN; i += NTH) {
            unsigned key = g_keys1[i];
            if (round == 0 || (key >> (shift + 8)) == pr)
                atomicAdd(&sh_h[(key >> shift) & 255u], 1u);
        }
        __syncthreads();
        if (t < 256 && sh_h[t]) atomicAdd(&g_hist[t], sh_h[t]);
        gridbar();
        if (blockIdx.x == 0) {       // parallel select via suffix-scan
            int k = (round == 0) ? KP1 : __ldcg(&g_kst);
            if (t < 256) { sh_h[t] = atomicAdd(&g_hist[t], 0u); g_hist[t] = 0; }
            __syncthreads();
            for (int off = 1; off < 256; off <<= 1) {
                unsigned add = 0;
                if (t < 256 && t + off < 256) add = sh_h[t + off];
                __syncthreads();
                if (t < 256) sh_h[t] += add;
                __syncthreads();
            }
            if (t < 256) {
                unsigned nxt = (t == 255) ? 0u : sh_h[t + 1];
                if (sh_h[t] >= (unsigned)k && nxt < (unsigned)k) {
                    unsigned np = (round == 0) ? (unsigned)t
                                               : ((__ldcg(&g_prefix) << 8) | (unsigned)t);
                    atomicExch(&g_prefix, np);
                    atomicExch((unsigned*)&g_kst, (unsigned)(k - (int)nxt));
                }
            }
        }
        gridbar();
    }
    unsigned th = __ldcg(&g_prefix);
    int T = (int)__ldcg((const unsigned*)&g_kst);

    // ---- poolcnt: chunk == block of 1024 ----
    for (int c = blockIdx.x; c < NCH; c += NB) {
        int i = c * 1024 + t;
        int cgt = 0, ceq = 0;
        if (i < NN) { unsigned k = g_keys1[i]; cgt = (k > th); ceq = (k == th); }
#pragma unroll
        for (int o = 16; o > 0; o >>= 1) {
            cgt += __shfl_down_sync(0xffffffffu, cgt, o);
            ceq += __shfl_down_sync(0xffffffffu, ceq, o);
        }
        __syncthreads();
        if (t == 0) { sg = 0; se = 0; }
        __syncthreads();
        if (lane == 0) { atomicAdd(&sg, cgt); atomicAdd(&se, ceq); }
        __syncthreads();
        if (t == 0) { g_cg[c] = sg; g_ce[c] = se; }
    }
    gridbar();
    if (blockIdx.x == 0) {
        int* s_cg = (int*)shx;
        int* s_ce = s_cg + 128;
        if (t < NCH) { s_cg[t] = __ldcg(&g_cg[t]); s_ce[t] = __ldcg(&g_ce[t]); }
        __syncthreads();
        if (t == 0) {
            int ceo = 0, ko = 0;
            for (int c = 0; c < NCH; c++) {
                g_ceOff[c] = ceo;
                int take = T - ceo; if (take < 0) take = 0; if (take > s_ce[c]) take = s_ce[c];
                g_keptOff[c] = ko;
                ko += s_cg[c] + take;
                ceo += s_ce[c];
            }
        }
    }
    gridbar();
    // ---- assign: stable index-order compaction, one pass per 1024-chunk ----
    for (int c = blockIdx.x; c < NCH; c += NB) {
        int ceoffc = g_ceOff[c], koffc = g_keptOff[c];
        int i = c * 1024 + t;
        int gt = 0, eq = 0;
        if (i < NN) { unsigned k = g_keys1[i]; gt = (k > th); eq = (k == th); }
        unsigned be = __ballot_sync(0xffffffffu, eq);
        int eqr = __popc(be & ((1u << lane) - 1u));
        __syncthreads();
        if (lane == 0) sw[wid] = __popc(be);
        __syncthreads();
        if (t == 0) { int ss = 0; for (int w = 0; w < 32; w++) { swo[w] = ss; ss += sw[w]; } }
        __syncthreads();
        eqr += swo[wid];
        int kept = gt || (eq && (ceoffc + eqr) < T);
        unsigned bk = __ballot_sync(0xffffffffu, kept);
        int kr = __popc(bk & ((1u << lane) - 1u));
        __syncthreads();
        if (lane == 0) sw[wid] = __popc(bk);
        __syncthreads();
        if (t == 0) { int ss = 0; for (int w = 0; w < 32; w++) { swo[w] = ss; ss += sw[w]; } }
        __syncthreads();
        kr += swo[wid];
        if (i < NN) {
            if (kept) g_sel1[koffc + kr] = i;
            g_inv1[i] = -1;
        }
        __syncthreads();
    }
    gridbar();
    // ---- ck1 ----
    for (int id = gid; id < KP1; id += NTH) {
        int v = g_sel1[id];
        g_ck[id] = ((unsigned long long)g_keys1[v] << 32) | (unsigned)(0xFFFFFFFFu - (unsigned)v);
        g_rank[id] = 0;
    }
    gridbar();
    // ---- rank1 (exact reference order): 1024 threads = 256 i-elems x 4 j-quarters ----
    for (int p = blockIdx.x; p < 256; p += NB) {
        int it = p & 15, jt = p >> 4;
        __syncthreads();
        if (t < 256) sj[t] = g_ck[jt * 256 + t];
        __syncthreads();
        int ii = t & 255, jq = t >> 8;
        unsigned long long ki = g_ck[it * 256 + ii];
        int cnt = 0;
#pragma unroll 8
        for (int j = jq * 64; j < jq * 64 + 64; j++) cnt += (sj[j] > ki);
        if (cnt) atomicAdd(&g_rank[it * 256 + ii], cnt);
    }
    gridbar();
    // ---- perm1 ----
    for (int id = gid; id < KP1; id += NTH) {
        int v = g_sel1[id];
        int r = __ldcg(&g_rank[id]);
        g_sel1s[r] = v;
        g_inv1[v] = r;
    }
    gridbar();
    // ---- x1p + filter ----
    for (int idx = gid; idx < KP1 * 64; idx += NTH) {
        int id = idx >> 6, f = idx & 63;
        int v = g_sel1s[id];
        double dd = g_ddinv[v], d2 = dd * dd;
        float c0 = (float)(g_dagg3[3 * v + 0] * dd + (double)pos[3 * v + 0] * d2);
        float c1 = (float)(g_dagg3[3 * v + 1] * dd + (double)pos[3 * v + 1] * d2);
        float c2 = (float)(g_dagg3[3 * v + 2] * dd + (double)pos[3 * v + 2] * d2);
        float score = ikey(g_keys1[v]);
        float val = b1[f] + c0 * W1[f] + c1 * W1[64 + f] + c2 * W1[128 + f];
        G_X1P[id * 64 + f] = leaky(val) * score;
    }
    {
        const int4* src4 = (const int4*)src;
        const int4* dst4 = (const int4*)dst;
        for (int q = gid; q < NE / 4; q += NTH) {
            int4 s4 = src4[q]; int4 d4 = dst4[q];
            int ss[4] = {s4.x, s4.y, s4.z, s4.w};
            int dd[4] = {d4.x, d4.y, d4.z, d4.w};
#pragma unroll
            for (int j = 0; j < 4; j++) {
                int ms = g_inv1[ss[j]];
                int md = g_inv1[dd[j]];
                if (ms >= 0 && md >= 0) {
                    int pp = atomicAdd(&g_ne1, 1);
                    if (pp < EC) g_edge[pp] = make_int2(ms, md);
                    atomicAdd(&g_dinv2[md], 1.0f);
                }
            }
        }
    }
    gridbar();
    for (int i = gid; i < KP1; i += NTH)
        g_dinv2[i] = 1.0f / sqrtf(g_dinv2[i] + 1.0f);
    gridbar();
    // ---- agg64 ----
    int ne = atomicAdd(&g_ne1, 0); if (ne > EC) ne = EC;
    for (int idx = gid; idx < ne * 64; idx += NTH) {
        int e = idx >> 6, f = idx & 63;
        int2 ed = g_edge[e];
        float nm = g_dinv2[ed.x] * g_dinv2[ed.y];
        atomicAdd(&G_AGG64[ed.y * 64 + f], G_X1P[ed.x * 64 + f] * nm);
    }
    gridbar();
    // ---- x2 tiles (16 nodes/tile, 256 tiles); 1024 threads: 2 nodes/thread ----
    for (int i = t; i < 64 * 128; i += NT) sW2[i] = W2[i];
    if (t < 128) sb2[t] = b2[t];
    __syncthreads();
    for (int tile = blockIdx.x; tile < 256; tile += NB) {
        int n0 = tile * 16;
        __syncthreads();
        if (t < 1024) {
            int n = t >> 6, c = t & 63;
            int node = n0 + n;
            float d = g_dinv2[node];
            shx[t] = G_AGG64[node * 64 + c] + G_X1P[node * 64 + c] * d * d;
        }
        __syncthreads();
        int tc = t & 127, nh = t >> 7;          // 8 node slots
#pragma unroll
        for (int g = 0; g < 2; g++) {
            int n = nh * 2 + g;
            float acc = sb2[tc];
#pragma unroll
            for (int c = 0; c < 64; c++) acc += shx[n * 64 + c] * sW2[c * 128 + tc];
            G_X2[(n0 + n) * 128 + tc] = leaky(acc);
        }
    }
    gridbar();
    // ---- agg128 (G_X2 aliases dagg3 read earlier -> bypass L1) ----
    for (int idx = gid; idx < ne * 128; idx += NTH) {
        int e = idx >> 7, f = idx & 127;
        int2 ed = g_edge[e];
        float nm = g_dinv2[ed.x] * g_dinv2[ed.y];
        atomicAdd(&G_AGG128[ed.y * 128 + f], __ldcg(&G_X2[ed.x * 128 + f]) * nm);
    }
}

// ---------------- 4) x3 + score2 (normal kernel, 512 blocks) ----------------
__global__ void k_x3s(const float* __restrict__ W3, const float* __restrict__ b3,
                      const float* __restrict__ p2) {
    __shared__ float sW[128 * 64];      // 32 KB
    __shared__ float sh[8 * 128];       // 4 KB
    __shared__ float sx3[8 * 256];      // 8 KB
    __shared__ float sb[256], sp[256];  // 2 KB
    int t = threadIdx.x;   // 256
    sb[t] = b3[t]; sp[t] = p2[t];
    int n0 = blockIdx.x * 8;
    for (int i = t; i < 8 * 128; i += 256) {
        int n = i >> 7, c = i & 127;
        int node = n0 + n;
        float d = g_dinv2[node];
        sh[i] = G_AGG128[node * 128 + c] + G_X2[node * 128 + c] * d * d;
    }
    int cc = t & 63, ng = t >> 6;
#pragma unroll 1
    for (int wt = 0; wt < 4; wt++) {
        __syncthreads();
        for (int i = t; i < 128 * 64; i += 256) {
            int c = i >> 6, w = i & 63;
            sW[i] = W3[c * 256 + wt * 64 + w];
        }
        __syncthreads();
        int col = wt * 64 + cc;
        float bb = sb[col];
#pragma unroll
        for (int g = 0; g < 2; g++) {
            int n = ng * 2 + g;
            float acc = bb;
#pragma unroll
            for (int c = 0; c < 128; c++) acc += sh[n * 128 + c] * sW[c * 64 + cc];
            sx3[n * 256 + col] = leaky(acc);
        }
    }
    __syncthreads();
    int w = t >> 5, lane = t & 31;
    double s = 0.0;
    for (int c = lane; c < 256; c += 32) s += (double)sx3[w * 256 + c] * (double)sp[c];
#pragma unroll
    for (int o = 16; o > 0; o >>= 1) s += __shfl_down_sync(0xffffffffu, s, o);
    if (lane == 0) {
        int node = n0 + w;
        float sc = tanhf((float)(s * g_invp2d));
        g_sc2[node] = sc;
        g_ck[node] = ((unsigned long long)fkey(sc) << 32) | (unsigned)(0xFFFFFFFFu - (unsigned)node);
        g_rank[node] = 0;
    }
}

// ---------------- 5) pool2 rank ----------------
__global__ void k_rank2() {
    int it = blockIdx.x & 15, jt = blockIdx.x >> 4;
    __shared__ unsigned long long sj[256];
    int t = threadIdx.x;
    sj[t] = g_ck[jt * 256 + t];
    __syncthreads();
    unsigned long long ki = g_ck[it * 256 + t];
    int cnt = 0;
#pragma unroll 8
    for (int j = 0; j < 256; j++) cnt += (sj[j] > ki);
    if (cnt) atomicAdd(&g_rank[it * 256 + t], cnt);
}

// ---------------- 6) gather: 4096 blocks, non-winners exit ----------------
__global__ void k_gather(const float* __restrict__ W3, const float* __restrict__ b3) {
    int n = blockIdx.x;            // node 0..4095
    int r = g_rank[n];
    if (r >= KP2) return;
    __shared__ float sh[128];
    int c = threadIdx.x;           // 256
    if (c < 128) {
        float d = g_dinv2[n];
        sh[c] = G_AGG128[n * 128 + c] + G_X2[n * 128 + c] * d * d;
    }
    __syncthreads();
    float ssc = g_sc2[n];
    float acc = b3[c];
#pragma unroll 8
    for (int k = 0; k < 128; k++) acc += sh[k] * W3[k * 256 + c];
    g_xflat[c * 256 + r] = leaky(acc) * ssc;
}

// ---------------- 7) FC: 2048 blocks x 128 threads, 32 rows/block ----------------
__global__ void k_fc(const float* __restrict__ W, float* __restrict__ out) {
    int t = threadIdx.x;           // 128, float4 cols
    int row0 = blockIdx.x * 32;
    const float4* W4 = (const float4*)W;
    float4 acc = make_float4(0.f, 0.f, 0.f, 0.f);
#pragma unroll 8
    for (int r = 0; r < 32; r++) {
        int row = row0 + r;
        float v = g_xflat[row];
        float4 w = __ldg(&W4[(size_t)row * 128 + t]);
        acc.x += v * w.x; acc.y += v * w.y; acc.z += v * w.z; acc.w += v * w.w;
    }
    atomicAdd(&out[t * 4 + 0], acc.x);
    atomicAdd(&out[t * 4 + 1], acc.y);
    atomicAdd(&out[t * 4 + 2], acc.z);
    atomicAdd(&out[t * 4 + 3], acc.w);
}

// ---------------- launch ----------------
extern "C" void kernel_launch(void* const* d_in, const int* in_sizes, int n_in,
                              void* d_out, int out_size) {
    const float* pos = (const float*)d_in[0];
    const int*   ei  = (const int*)d_in[1];      // int32 edge_index
    const float* W1  = (const float*)d_in[2];
    const float* b1  = (const float*)d_in[3];
    const float* W2  = (const float*)d_in[4];
    const float* b2  = (const float*)d_in[5];
    const float* W3  = (const float*)d_in[6];
    const float* b3  = (const float*)d_in[7];
    const float* p1  = (const float*)d_in[8];
    const float* p2  = (const float*)d_in[9];
    const float* fcW = (const float*)d_in[10];
    const float* fcb = (const float*)d_in[11];
    float* out = (float*)d_out;
    (void)n_in; (void)in_sizes; (void)out_size;

    const int* src = ei;
    const int* dst = ei + NE;

    k_setup<<<512, 256>>>(p1, p2, fcb, out);
    k_conv1<<<NB, NT>>>(src, dst, pos, W1, b1, p1);
    k_pool1<<<NB, NT>>>(src, dst, pos, W1, b1, W2, b2);
    k_x3s<<<KP1 / 8, 256>>>(W3, b3, p2);
    k_rank2<<<256, 256>>>();
    k_gather<<<KP1, 256>>>(W3, b3);
    k_fc<<<2048, 128>>>(fcW, out);
}

// round 14
// speedup vs baseline: 1.7213x; 1.7213x over previous
#include <cuda_runtime.h>
#include <math.h>

#define NN 100000
#define NE 1200000
#define KP1 4096
#define KP2 256
#define SLOPE 0.01f
#define EC 65536
#define NB 148
#define NT 256
#define NTH (NB*NT)
#define NCH 98            // ceil(NN/1024), chunk = 1024

// ---------------- scratch (no allocations) ----------------
__device__ int      g_degi[NN];
__device__ double   g_ddinv[NN];
__device__ double   g_dagg3[NN * 3];       // aliased later as x2 floats
__device__ unsigned g_keys1[NN];
__device__ int      g_inv1[NN];
__device__ float    g_B[524288];           // [x1p | agg64]
__device__ float    g_C[524288];           // agg128

#define G_X2     ((float*)g_dagg3)         /* [KP1*128] after dagg3 dead */
#define G_X1P    (g_B)
#define G_AGG64  (g_B + 262144)
#define G_AGG128 (g_C)

__device__ unsigned g_hist[256];
__device__ unsigned g_prefix;
__device__ int      g_kst;
__device__ int      g_cg[NCH], g_ce[NCH], g_ceOff[NCH], g_keptOff[NCH];
__device__ int      g_sel1[KP1], g_sel1s[KP1];
__device__ unsigned long long g_ck[KP1];
__device__ int      g_rank[KP1];
__device__ int2     g_edge[EC];
__device__ int      g_ne1;
__device__ float    g_dinv2[KP1];
__device__ float    g_sc2[KP1];
__device__ float    g_xflat[KP2 * 256];
__device__ float    g_invp1;
__device__ double   g_invp2d;
__device__ unsigned g_barc, g_barg;        // zero-init; self-resetting

__device__ __forceinline__ float leaky(float v) { return v > 0.f ? v : SLOPE * v; }
__device__ __forceinline__ unsigned fkey(float f) {
    unsigned u = __float_as_uint(f);
    return (u & 0x80000000u) ? ~u : (u | 0x80000000u);
}
__device__ __forceinline__ float ikey(unsigned k) {
    return __uint_as_float((k & 0x80000000u) ? (k ^ 0x80000000u) : ~k);
}

// software grid barrier: NB blocks, all resident -> no deadlock.
__device__ __forceinline__ void gridbar() {
    __syncthreads();
    if (threadIdx.x == 0) {
        unsigned gen = atomicAdd(&g_barg, 0u);
        __threadfence();
        if (atomicAdd(&g_barc, 1u) == NB - 1u) {
            atomicExch(&g_barc, 0u);
            __threadfence();
            atomicAdd(&g_barg, 1u);
        } else {
            while (atomicAdd(&g_barg, 0u) == gen) __nanosleep(64);
        }
        __threadfence();
    }
    __syncthreads();
}

// ---------------- 0) setup ----------------
__global__ void k_setup(const float* __restrict__ p1, const float* __restrict__ p2,
                        const float* __restrict__ fcb, float* __restrict__ out) {
    int gid = blockIdx.x * blockDim.x + threadIdx.x;
    int st = gridDim.x * blockDim.x;
    for (int i = gid; i < NN; i += st) g_degi[i] = 0;
    for (int i = gid; i < NN * 3; i += st) g_dagg3[i] = 0.0;
    for (int i = gid; i < KP1; i += st) g_dinv2[i] = 0.f;
    if (gid < 256) g_hist[gid] = 0;
    if (gid < 512) out[gid] = fcb[gid];
    if (blockIdx.x == 0) {
        int t = threadIdx.x;
        if (t == 0) g_ne1 = 0;
        if (t < 32) {                          // warp 0: ||p1||
            double s = 0.0;
            for (int i = t; i < 64; i += 32) { double v = (double)p1[i]; s += v * v; }
#pragma unroll
            for (int o = 16; o > 0; o >>= 1) s += __shfl_down_sync(0xffffffffu, s, o);
            if (t == 0) g_invp1 = (float)(1.0 / sqrt(s));
        } else if (t < 64) {                   // warp 1: ||p2||
            int lane = t & 31;
            double s = 0.0;
            for (int i = lane; i < 256; i += 32) { double v = (double)p2[i]; s += v * v; }
#pragma unroll
            for (int o = 16; o > 0; o >>= 1) s += __shfl_down_sync(0xffffffffu, s, o);
            if (lane == 0) g_invp2d = 1.0 / sqrt(s);
        }
    }
}

// ---------------- 1) deg ----------------
__global__ void k_deg(const int* __restrict__ dst) {
    int q = blockIdx.x * blockDim.x + threadIdx.x;
    if (q >= NE / 4) return;
    int4 d = ((const int4*)dst)[q];
    atomicAdd(&g_degi[d.x], 1); atomicAdd(&g_degi[d.y], 1);
    atomicAdd(&g_degi[d.z], 1); atomicAdd(&g_degi[d.w], 1);
}
// ---------------- 2) dinv ----------------
__global__ void k_dinv() {
    int i = blockIdx.x * blockDim.x + threadIdx.x;
    if (i < NN) g_ddinv[i] = 1.0 / sqrt((double)g_degi[i] + 1.0);
}
// ---------------- 3,4) zero B-upper / C ----------------
__global__ void k_zB() {
    for (int i = blockIdx.x * blockDim.x + threadIdx.x; i < 262144; i += gridDim.x * blockDim.x)
        g_B[262144 + i] = 0.f;
}
__global__ void k_zC() {
    for (int i = blockIdx.x * blockDim.x + threadIdx.x; i < 524288; i += gridDim.x * blockDim.x)
        g_C[i] = 0.f;
}
// ---------------- 5) agg3 (double atomics) — ncu sample slot ----------------
__global__ void k_agg3(const int* __restrict__ src, const int* __restrict__ dst,
                       const float* __restrict__ pos) {
    int q = blockIdx.x * blockDim.x + threadIdx.x;
    if (q >= NE / 4) return;
    int4 s4 = ((const int4*)src)[q];
    int4 d4 = ((const int4*)dst)[q];
    int ss[4] = {s4.x, s4.y, s4.z, s4.w};
    int dd[4] = {d4.x, d4.y, d4.z, d4.w};
#pragma unroll
    for (int j = 0; j < 4; j++) {
        int s = ss[j], d = dd[j];
        double ds = g_ddinv[s];
        atomicAdd(&g_dagg3[d * 3 + 0], (double)pos[s * 3 + 0] * ds);
        atomicAdd(&g_dagg3[d * 3 + 1], (double)pos[s * 3 + 1] * ds);
        atomicAdd(&g_dagg3[d * 3 + 2], (double)pos[s * 3 + 2] * ds);
    }
}
// ---------------- 6) score1 ----------------
__global__ void k_score1(const float* __restrict__ pos, const float* __restrict__ W1,
                         const float* __restrict__ b1, const float* __restrict__ p1) {
    __shared__ float sW[192], sb[64], sp[64];
    int t = threadIdx.x;   // 256
    if (t < 192) sW[t] = W1[t];
    if (t < 64) { sb[t] = b1[t]; sp[t] = p1[t]; }
    __syncthreads();
    int i = blockIdx.x * blockDim.x + t;
    if (i >= NN) return;
    double dd = g_ddinv[i], d2 = dd * dd;
    float c0 = (float)(g_dagg3[3 * i + 0] * dd + (double)pos[3 * i + 0] * d2);
    float c1 = (float)(g_dagg3[3 * i + 1] * dd + (double)pos[3 * i + 1] * d2);
    float c2 = (float)(g_dagg3[3 * i + 2] * dd + (double)pos[3 * i + 2] * d2);
    float s = 0.f;
#pragma unroll
    for (int f = 0; f < 64; f++) {
        float v = sb[f] + c0 * sW[f] + c1 * sW[64 + f] + c2 * sW[128 + f];
        s += leaky(v) * sp[f];
    }
    g_keys1[i] = fkey(tanhf(s * g_invp1));
}

// ---------------- 7) cooperative: radix select + compaction + rank1 + perm1 ----------------
__global__ void __launch_bounds__(NT, 1)
k_radixsel() {
    int t = threadIdx.x, gid = blockIdx.x * NT + t;
    int lane = t & 31, wid = t >> 5;
    __shared__ unsigned sh_h[256];
    __shared__ int sw[8], swo[8];
    __shared__ int sg, se;
    __shared__ int s_cg[128], s_ce[128];
    __shared__ unsigned long long sj[256];

    // ---- radix select: 4 rounds of 8 bits ----
#pragma unroll 1
    for (int round = 0; round < 4; round++) {
        int shift = 24 - 8 * round;
        sh_h[t] = 0;
        __syncthreads();
        unsigned pr = (round == 0) ? 0u : __ldcg(&g_prefix);
        for (int i = gid; i < NN; i += NTH) {
            unsigned key = g_keys1[i];
            if (round == 0 || (key >> (shift + 8)) == pr)
                atomicAdd(&sh_h[(key >> shift) & 255u], 1u);
        }
        __syncthreads();
        if (sh_h[t]) atomicAdd(&g_hist[t], sh_h[t]);
        gridbar();
        if (blockIdx.x == 0) {       // parallel select via suffix-scan
            int k = (round == 0) ? KP1 : __ldcg(&g_kst);
            sh_h[t] = atomicAdd(&g_hist[t], 0u);
            g_hist[t] = 0;
            __syncthreads();
            for (int off = 1; off < 256; off <<= 1) {
                unsigned add = (t + off < 256) ? sh_h[t + off] : 0u;
                __syncthreads();
                sh_h[t] += add;
                __syncthreads();
            }
            unsigned nxt = (t == 255) ? 0u : sh_h[t + 1];
            if (sh_h[t] >= (unsigned)k && nxt < (unsigned)k) {
                unsigned np = (round == 0) ? (unsigned)t
                                           : ((__ldcg(&g_prefix) << 8) | (unsigned)t);
                atomicExch(&g_prefix, np);
                atomicExch((unsigned*)&g_kst, (unsigned)(k - (int)nxt));
            }
        }
        gridbar();
    }
    unsigned th = __ldcg(&g_prefix);
    int T = (int)__ldcg((const unsigned*)&g_kst);

    // ---- poolcnt: per 1024-chunk gt/eq totals (4 sub-steps of 256) ----
    for (int c = blockIdx.x; c < NCH; c += NB) {
        int cgt = 0, ceq = 0;
#pragma unroll
        for (int s = 0; s < 4; s++) {
            int i = c * 1024 + s * 256 + t;
            if (i < NN) { unsigned k = g_keys1[i]; cgt += (k > th); ceq += (k == th); }
        }
#pragma unroll
        for (int o = 16; o > 0; o >>= 1) {
            cgt += __shfl_down_sync(0xffffffffu, cgt, o);
            ceq += __shfl_down_sync(0xffffffffu, ceq, o);
        }
        __syncthreads();
        if (t == 0) { sg = 0; se = 0; }
        __syncthreads();
        if (lane == 0) { atomicAdd(&sg, cgt); atomicAdd(&se, ceq); }
        __syncthreads();
        if (t == 0) { g_cg[c] = sg; g_ce[c] = se; }
    }
    gridbar();
    if (blockIdx.x == 0) {
        if (t < NCH) { s_cg[t] = __ldcg(&g_cg[t]); s_ce[t] = __ldcg(&g_ce[t]); }
        __syncthreads();
        if (t == 0) {
            int ceo = 0, ko = 0;
            for (int c = 0; c < NCH; c++) {
                g_ceOff[c] = ceo;
                int take = T - ceo; if (take < 0) take = 0; if (take > s_ce[c]) take = s_ce[c];
                g_keptOff[c] = ko;
                ko += s_cg[c] + take;
                ceo += s_ce[c];
            }
        }
    }
    gridbar();
    // ---- assign: stable index-order compaction (4 sub-rounds per 1024-chunk) ----
    for (int c = blockIdx.x; c < NCH; c += NB) {
        int ceoffc = g_ceOff[c], koffc = g_keptOff[c];
        int base_eq = 0, base_kept = 0;
#pragma unroll 1
        for (int s = 0; s < 4; s++) {
            int i = c * 1024 + s * 256 + t;
            int gt = 0, eq = 0;
            if (i < NN) { unsigned k = g_keys1[i]; gt = (k > th); eq = (k == th); }
            unsigned be = __ballot_sync(0xffffffffu, eq);
            int eqr = __popc(be & ((1u << lane) - 1u));
            __syncthreads();
            if (lane == 0) sw[wid] = __popc(be);
            __syncthreads();
            if (t == 0) { int ss = 0; for (int w = 0; w < 8; w++) { swo[w] = ss; ss += sw[w]; } sg = ss; }
            __syncthreads();
            eqr += swo[wid];
            int kept = gt || (eq && (ceoffc + base_eq + eqr) < T);
            unsigned bk = __ballot_sync(0xffffffffu, kept);
            int kr = __popc(bk & ((1u << lane) - 1u));
            __syncthreads();
            if (lane == 0) sw[wid] = __popc(bk);
            __syncthreads();
            if (t == 0) { int ss = 0; for (int w = 0; w < 8; w++) { swo[w] = ss; ss += sw[w]; } se = ss; }
            __syncthreads();
            kr += swo[wid];
            if (i < NN) {
                if (kept) g_sel1[koffc + base_kept + kr] = i;
                g_inv1[i] = -1;
            }
            __syncthreads();
            base_eq += sg; base_kept += se;
        }
    }
    gridbar();
    // ---- ck1 ----
    for (int id = gid; id < KP1; id += NTH) {
        int v = g_sel1[id];
        g_ck[id] = ((unsigned long long)g_keys1[v] << 32) | (unsigned)(0xFFFFFFFFu - (unsigned)v);
        g_rank[id] = 0;
    }
    gridbar();
    // ---- rank1 (exact reference order) ----
    for (int p = blockIdx.x; p < 256; p += NB) {
        int it = p & 15, jt = p >> 4;
        __syncthreads();
        sj[t] = g_ck[jt * 256 + t];
        __syncthreads();
        unsigned long long ki = g_ck[it * 256 + t];
        int cnt = 0;
#pragma unroll 8
        for (int j = 0; j < 256; j++) cnt += (sj[j] > ki);
        if (cnt) atomicAdd(&g_rank[it * 256 + t], cnt);
    }
    gridbar();
    // ---- perm1 ----
    for (int id = gid; id < KP1; id += NTH) {
        int v = g_sel1[id];
        int r = __ldcg(&g_rank[id]);
        g_sel1s[r] = v;
        g_inv1[v] = r;
    }
}

// ---------------- 8) x1p ----------------
__global__ void k_x1p(const float* __restrict__ pos, const float* __restrict__ W1,
                      const float* __restrict__ b1) {
    int idx = blockIdx.x * blockDim.x + threadIdx.x;
    if (idx >= KP1 * 64) return;
    int id = idx >> 6, f = idx & 63;
    int v = g_sel1s[id];
    double dd = g_ddinv[v], d2 = dd * dd;
    float c0 = (float)(g_dagg3[3 * v + 0] * dd + (double)pos[3 * v + 0] * d2);
    float c1 = (float)(g_dagg3[3 * v + 1] * dd + (double)pos[3 * v + 1] * d2);
    float c2 = (float)(g_dagg3[3 * v + 2] * dd + (double)pos[3 * v + 2] * d2);
    float score = ikey(g_keys1[v]);
    float val = b1[f] + c0 * W1[f] + c1 * W1[64 + f] + c2 * W1[128 + f];
    G_X1P[id * 64 + f] = leaky(val) * score;
}
// ---------------- 9) filter ----------------
__global__ void k_filter(const int* __restrict__ src, const int* __restrict__ dst) {
    int q = blockIdx.x * blockDim.x + threadIdx.x;
    if (q >= NE / 4) return;
    int4 s4 = ((const int4*)src)[q];
    int4 d4 = ((const int4*)dst)[q];
    int ss[4] = {s4.x, s4.y, s4.z, s4.w};
    int dd[4] = {d4.x, d4.y, d4.z, d4.w};
#pragma unroll
    for (int j = 0; j < 4; j++) {
        int ms = g_inv1[ss[j]];
        int md = g_inv1[dd[j]];
        if (ms >= 0 && md >= 0) {
            int p = atomicAdd(&g_ne1, 1);
            if (p < EC) g_edge[p] = make_int2(ms, md);
            atomicAdd(&g_dinv2[md], 1.0f);
        }
    }
}
// ---------------- 10) dinv2 ----------------
__global__ void k_dinv2() {
    int i = blockIdx.x * blockDim.x + threadIdx.x;
    if (i < KP1) g_dinv2[i] = 1.0f / sqrtf(g_dinv2[i] + 1.0f);
}
// ---------------- 11) agg64 ----------------
__global__ void k_agg64() {
    int ne = g_ne1; if (ne > EC) ne = EC;
    for (int idx = blockIdx.x * blockDim.x + threadIdx.x; idx < ne * 64; idx += gridDim.x * blockDim.x) {
        int e = idx >> 6, f = idx & 63;
        int2 ed = g_edge[e];
        float nm = g_dinv2[ed.x] * g_dinv2[ed.y];
        atomicAdd(&G_AGG64[ed.y * 64 + f], G_X1P[ed.x * 64 + f] * nm);
    }
}
// ---------------- 12) x2: register-tiled, 16 nodes/block, thread=col ----------------
__global__ void k_x2(const float* __restrict__ W2, const float* __restrict__ b2) {
    __shared__ float sh[16 * 64];
    int t = threadIdx.x;          // 128 cols
    int n0 = blockIdx.x * 16;
    for (int i = t; i < 16 * 64; i += 128) {
        int n = i >> 6, c = i & 63;
        int node = n0 + n;
        float d = g_dinv2[node];
        sh[i] = G_AGG64[node * 64 + c] + G_X1P[node * 64 + c] * d * d;
    }
    __syncthreads();
    float acc[16];
    float bb = b2[t];
#pragma unroll
    for (int n = 0; n < 16; n++) acc[n] = bb;
#pragma unroll 4
    for (int c = 0; c < 64; c++) {
        float w = __ldg(&W2[c * 128 + t]);
#pragma unroll
        for (int n = 0; n < 16; n++) acc[n] += sh[n * 64 + c] * w;
    }
#pragma unroll
    for (int n = 0; n < 16; n++) G_X2[(n0 + n) * 128 + t] = leaky(acc[n]);
}
// ---------------- 13) agg128 ----------------
__global__ void k_agg128() {
    int ne = g_ne1; if (ne > EC) ne = EC;
    for (int idx = blockIdx.x * blockDim.x + threadIdx.x; idx < ne * 128; idx += gridDim.x * blockDim.x) {
        int e = idx >> 7, f = idx & 127;
        int2 ed = g_edge[e];
        float nm = g_dinv2[ed.x] * g_dinv2[ed.y];
        atomicAdd(&G_AGG128[ed.y * 128 + f], G_X2[ed.x * 128 + f] * nm);
    }
}
// ---------------- 14) x3 + score2: register-tiled, 16 nodes/block ----------------
__global__ void k_x3s(const float* __restrict__ W3, const float* __restrict__ b3,
                      const float* __restrict__ p2) {
    __shared__ float sh[16 * 128];      // 8 KB inputs
    __shared__ float sx3[16 * 256];     // 16 KB outputs
    __shared__ float sp[256];
    int t = threadIdx.x;                // 256 cols
    sp[t] = p2[t];
    int n0 = blockIdx.x * 16;
    for (int i = t; i < 16 * 128; i += 256) {
        int n = i >> 7, c = i & 127;
        int node = n0 + n;
        float d = g_dinv2[node];
        sh[i] = G_AGG128[node * 128 + c] + G_X2[node * 128 + c] * d * d;
    }
    __syncthreads();
    float acc[16];
    float bb = b3[t];
#pragma unroll
    for (int n = 0; n < 16; n++) acc[n] = bb;
#pragma unroll 4
    for (int k = 0; k < 128; k++) {
        float w = __ldg(&W3[k * 256 + t]);
#pragma unroll
        for (int n = 0; n < 16; n++) acc[n] += sh[n * 128 + k] * w;
    }
#pragma unroll
    for (int n = 0; n < 16; n++) sx3[n * 256 + t] = leaky(acc[n]);
    __syncthreads();
    // score: warp w handles nodes 2w, 2w+1
    int w = t >> 5, lane = t & 31;
    double ip2 = g_invp2d;
#pragma unroll
    for (int g = 0; g < 2; g++) {
        int n = w * 2 + g;
        double s = 0.0;
        for (int c = lane; c < 256; c += 32) s += (double)sx3[n * 256 + c] * (double)sp[c];
#pragma unroll
        for (int o = 16; o > 0; o >>= 1) s += __shfl_down_sync(0xffffffffu, s, o);
        if (lane == 0) {
            int node = n0 + n;
            float sc = tanhf((float)(s * ip2));
            g_sc2[node] = sc;
            g_ck[node] = ((unsigned long long)fkey(sc) << 32) | (unsigned)(0xFFFFFFFFu - (unsigned)node);
            g_rank[node] = 0;
        }
    }
}
// ---------------- 15) rank2 ----------------
__global__ void k_rank2() {
    int it = blockIdx.x & 15, jt = blockIdx.x >> 4;
    __shared__ unsigned long long sj[256];
    int t = threadIdx.x;
    sj[t] = g_ck[jt * 256 + t];
    __syncthreads();
    unsigned long long ki = g_ck[it * 256 + t];
    int cnt = 0;
#pragma unroll 8
    for (int j = 0; j < 256; j++) cnt += (sj[j] > ki);
    if (cnt) atomicAdd(&g_rank[it * 256 + t], cnt);
}
// ---------------- 16) gather ----------------
__global__ void k_gather(const float* __restrict__ W3, const float* __restrict__ b3) {
    int n = blockIdx.x;            // node 0..4095
    int r = g_rank[n];
    if (r >= KP2) return;
    __shared__ float sh[128];
    int c = threadIdx.x;           // 256
    if (c < 128) {
        float d = g_dinv2[n];
        sh[c] = G_AGG128[n * 128 + c] + G_X2[n * 128 + c] * d * d;
    }
    __syncthreads();
    float ssc = g_sc2[n];
    float acc = b3[c];
#pragma unroll 8
    for (int k = 0; k < 128; k++) acc += sh[k] * W3[k * 256 + c];
    g_xflat[c * 256 + r] = leaky(acc) * ssc;
}
// ---------------- 17) FC ----------------
__global__ void k_fc(const float* __restrict__ W, float* __restrict__ out) {
    int t = threadIdx.x;           // 128, float4 cols
    int row0 = blockIdx.x * 32;
    const float4* W4 = (const float4*)W;
    float4 acc = make_float4(0.f, 0.f, 0.f, 0.f);
#pragma unroll 8
    for (int r = 0; r < 32; r++) {
        int row = row0 + r;
        float v = g_xflat[row];
        float4 w = __ldg(&W4[(size_t)row * 128 + t]);
        acc.x += v * w.x; acc.y += v * w.y; acc.z += v * w.z; acc.w += v * w.w;
    }
    atomicAdd(&out[t * 4 + 0], acc.x);
    atomicAdd(&out[t * 4 + 1], acc.y);
    atomicAdd(&out[t * 4 + 2], acc.z);
    atomicAdd(&out[t * 4 + 3], acc.w);
}

// ---------------- launch ----------------
extern "C" void kernel_launch(void* const* d_in, const int* in_sizes, int n_in,
                              void* d_out, int out_size) {
    const float* pos = (const float*)d_in[0];
    const int*   ei  = (const int*)d_in[1];      // int32 edge_index
    const float* W1  = (const float*)d_in[2];
    const float* b1  = (const float*)d_in[3];
    const float* W2  = (const float*)d_in[4];
    const float* b2  = (const float*)d_in[5];
    const float* W3  = (const float*)d_in[6];
    const float* b3  = (const float*)d_in[7];
    const float* p1  = (const float*)d_in[8];
    const float* p2  = (const float*)d_in[9];
    const float* fcW = (const float*)d_in[10];
    const float* fcb = (const float*)d_in[11];
    float* out = (float*)d_out;
    (void)n_in; (void)in_sizes; (void)out_size;

    const int* src = ei;
    const int* dst = ei + NE;
    int eg4 = (NE / 4 + 255) / 256;       // 1172

    k_setup<<<512, 256>>>(p1, p2, fcb, out);          // 0
    k_deg<<<eg4, 256>>>(dst);                         // 1
    k_dinv<<<(NN + 255) / 256, 256>>>();              // 2
    k_zB<<<256, 256>>>();                             // 3
    k_zC<<<512, 256>>>();                             // 4
    k_agg3<<<eg4, 256>>>(src, dst, pos);              // 5  <- ncu sample
    k_score1<<<(NN + 255) / 256, 256>>>(pos, W1, b1, p1); // 6
    k_radixsel<<<NB, NT>>>();                         // 7
    k_x1p<<<1024, 256>>>(pos, W1, b1);                // 8
    k_filter<<<eg4, 256>>>(src, dst);                 // 9
    k_dinv2<<<16, 256>>>();                           // 10
    k_agg64<<<256, 256>>>();                          // 11
    k_x2<<<KP1 / 16, 128>>>(W2, b2);                  // 12
    k_agg128<<<256, 256>>>();                         // 13
    k_x3s<<<KP1 / 16, 256>>>(W3, b3, p2);             // 14
    k_rank2<<<256, 256>>>();                          // 15
    k_gather<<<KP1, 256>>>(W3, b3);                   // 16
    k_fc<<<2048, 128>>>(fcW, out);                    // 17
}